// round 8
// baseline (speedup 1.0000x reference)
#include <cuda_runtime.h>
#include <cuda_fp16.h>

#define N_NODES  100000
#define N_EDGES  3200000
#define IN_DIM   128
#define H1       32
#define H2       16
#define N_GRAPHS 512

#define GEMM_TM      64
#define GEMM_BLOCKS  ((N_NODES + GEMM_TM - 1) / GEMM_TM)      // 1563
#define E8           (N_EDGES / 8)                             // 400000
#define EDGE_BLOCKS  ((E8 + 255) / 256)                        // 1563
#define SCAN_BLOCKS  ((N_NODES + 255) / 256)                   // 391
#define SCALE_VEC    (N_NODES * H1 / 8)                        // 400000
#define SCALE_BLOCKS ((SCALE_VEC + 255) / 256)                 // 1563

// ---------------- scratch (static __device__ arrays — no allocation) ----------------
__device__ __align__(128) int    d_deg[N_NODES];
__device__ __align__(128) int    d_rowptr[N_NODES + 1];
__device__ __align__(128) int    d_cursor[N_NODES];
__device__ __align__(128) int    d_col[N_EDGES];
__device__ __align__(128) float  d_dinv[N_NODES];
__device__ __align__(128) float  d_g1[(size_t)N_NODES * H1];    // fp32 raw x@W1
__device__ __align__(128) __half d_g1h[(size_t)N_NODES * H1];   // fp16 dinv*(x@W1)
__device__ __align__(128) __half d_g2h[(size_t)N_NODES * H2];   // fp16 dinv*(h1@W2)
__device__ __align__(128) float  d_pool[N_GRAPHS * H2];
// decoupled-lookback scan state
__device__ int          d_ticket;
__device__ volatile int d_flag[SCAN_BLOCKS];
__device__ volatile int d_agg[SCAN_BLOCKS];
__device__ volatile int d_pref[SCAN_BLOCKS];

// ---------------- 1. zero accumulators + scan state ----------------
__global__ void k_zero() {
    int i = blockIdx.x * blockDim.x + threadIdx.x;
    if (i < N_NODES) d_deg[i] = 0;
    if (i < N_GRAPHS * H2) d_pool[i] = 0.f;
    if (i < SCAN_BLOCKS) d_flag[i] = 0;
    if (i == 0) d_ticket = 0;
}

// ---------------- 2. fused: raw GEMM (g1 = x @ W1) || degree histogram (ILP x8) ------
__global__ void __launch_bounds__(256) k_gemm_deg(const float* __restrict__ x,
                                                  const float* __restrict__ W1,
                                                  const int* __restrict__ ei) {
    if (blockIdx.x >= GEMM_BLOCKS) {
        int i = (blockIdx.x - GEMM_BLOCKS) * 256 + threadIdx.x;
        if (i < E8) {
            const int4* d4 = (const int4*)(ei + N_EDGES);
            int4 a = d4[2 * i], b = d4[2 * i + 1];
            if ((unsigned)a.x < N_NODES) atomicAdd(&d_deg[a.x], 1);
            if ((unsigned)a.y < N_NODES) atomicAdd(&d_deg[a.y], 1);
            if ((unsigned)a.z < N_NODES) atomicAdd(&d_deg[a.z], 1);
            if ((unsigned)a.w < N_NODES) atomicAdd(&d_deg[a.w], 1);
            if ((unsigned)b.x < N_NODES) atomicAdd(&d_deg[b.x], 1);
            if ((unsigned)b.y < N_NODES) atomicAdd(&d_deg[b.y], 1);
            if ((unsigned)b.z < N_NODES) atomicAdd(&d_deg[b.z], 1);
            if ((unsigned)b.w < N_NODES) atomicAdd(&d_deg[b.w], 1);
        }
        return;
    }
    __shared__ float xs[GEMM_TM * 132];
    int tid = threadIdx.x;
    int n0 = blockIdx.x * GEMM_TM;
    for (int i = tid; i < GEMM_TM * (IN_DIM / 4); i += 256) {
        int r = i >> 5, c = i & 31;
        float4 v = make_float4(0.f, 0.f, 0.f, 0.f);
        if (n0 + r < N_NODES)
            v = ((const float4*)(x + (size_t)(n0 + r) * IN_DIM))[c];
        *((float4*)(xs + r * 132 + c * 4)) = v;
    }
    __syncthreads();
    int tx = tid & 7;
    int ty = tid >> 3;
    const float* xr0 = xs + (2 * ty) * 132;
    const float* xr1 = xs + (2 * ty + 1) * 132;
    float a00 = 0.f, a01 = 0.f, a02 = 0.f, a03 = 0.f;
    float a10 = 0.f, a11 = 0.f, a12 = 0.f, a13 = 0.f;
    const float4* Wv = (const float4*)(W1) + tx;
#pragma unroll 8
    for (int k = 0; k < IN_DIM; k++) {
        float4 w = __ldg(Wv + k * 8);
        float p0 = xr0[k], p1 = xr1[k];
        a00 = fmaf(p0, w.x, a00); a01 = fmaf(p0, w.y, a01);
        a02 = fmaf(p0, w.z, a02); a03 = fmaf(p0, w.w, a03);
        a10 = fmaf(p1, w.x, a10); a11 = fmaf(p1, w.y, a11);
        a12 = fmaf(p1, w.z, a12); a13 = fmaf(p1, w.w, a13);
    }
    int n = n0 + 2 * ty;
    if (n < N_NODES)
        *((float4*)(d_g1 + (size_t)n * H1 + 4 * tx)) = make_float4(a00, a01, a02, a03);
    if (n + 1 < N_NODES)
        *((float4*)(d_g1 + (size_t)(n + 1) * H1 + 4 * tx)) = make_float4(a10, a11, a12, a13);
}

// ---------------- 3. single-pass decoupled-lookback scan ----------------
__global__ void __launch_bounds__(256) k_scan() {
    __shared__ int s_bid, s_total, s_run;
    __shared__ int wsum[8], woff[8];
    int t = threadIdx.x;
    if (t == 0) s_bid = atomicAdd(&d_ticket, 1);
    __syncthreads();
    int b = s_bid;
    int i = b * 256 + t;
    int v = (i < N_NODES) ? d_deg[i] : 0;
    int lane = t & 31, wid = t >> 5;
    int x = v;
#pragma unroll
    for (int off = 1; off < 32; off <<= 1) {
        int y = __shfl_up_sync(0xffffffffu, x, off);
        if (lane >= off) x += y;
    }
    if (lane == 31) wsum[wid] = x;
    __syncthreads();
    if (t == 0) {
        int r = 0;
#pragma unroll
        for (int j = 0; j < 8; j++) { woff[j] = r; r += wsum[j]; }
        s_total = r;
        d_agg[b] = r;
        __threadfence();
        if (b == 0) { d_pref[0] = r; __threadfence(); d_flag[0] = 2; s_run = 0; }
        else        { d_flag[b] = 1; }
    }
    __syncthreads();
    int total = s_total;
    if (b > 0 && wid == 0) {
        int run = 0;
        int p = b - 1;
        while (true) {
            int idx = p - lane;
            int f = 0, a = 0;
            if (idx >= 0) {
                do { f = d_flag[idx]; } while (f == 0);
                a = (f == 2) ? d_pref[idx] : d_agg[idx];
            }
            unsigned pm = __ballot_sync(0xffffffffu, idx >= 0 && f == 2);
            int stop = pm ? (__ffs(pm) - 1) : 31;
            int contrib = (idx >= 0 && lane <= stop) ? a : 0;
#pragma unroll
            for (int off = 16; off; off >>= 1)
                contrib += __shfl_xor_sync(0xffffffffu, contrib, off);
            run += contrib;
            if (pm) break;
            p -= 32;
        }
        if (lane == 0) {
            d_pref[b] = run + total;
            __threadfence();
            d_flag[b] = 2;
            s_run = run;
        }
    }
    __syncthreads();
    int excl = s_run + woff[wid] + (x - v);
    if (i < N_NODES) {
        d_rowptr[i] = excl;
        d_cursor[i] = excl;
        d_dinv[i] = rsqrtf((float)(v + 1));
        if (i == N_NODES - 1) d_rowptr[N_NODES] = excl + v;
    }
}

// ---------------- 4. fused: CSR fill (ILP x8) || g1h = half(dinv * g1) ----------------
__global__ void __launch_bounds__(256) k_csr_scale(const int* __restrict__ ei) {
    if (blockIdx.x < EDGE_BLOCKS) {
        int i = blockIdx.x * 256 + threadIdx.x;
        if (i < E8) {
            const int4* s4 = (const int4*)ei;
            const int4* d4 = (const int4*)(ei + N_EDGES);
            int4 s0 = s4[2 * i], s1 = s4[2 * i + 1];
            int4 dd0 = d4[2 * i], dd1 = d4[2 * i + 1];
            if ((unsigned)dd0.x < N_NODES && (unsigned)s0.x < N_NODES)
                d_col[atomicAdd(&d_cursor[dd0.x], 1)] = s0.x;
            if ((unsigned)dd0.y < N_NODES && (unsigned)s0.y < N_NODES)
                d_col[atomicAdd(&d_cursor[dd0.y], 1)] = s0.y;
            if ((unsigned)dd0.z < N_NODES && (unsigned)s0.z < N_NODES)
                d_col[atomicAdd(&d_cursor[dd0.z], 1)] = s0.z;
            if ((unsigned)dd0.w < N_NODES && (unsigned)s0.w < N_NODES)
                d_col[atomicAdd(&d_cursor[dd0.w], 1)] = s0.w;
            if ((unsigned)dd1.x < N_NODES && (unsigned)s1.x < N_NODES)
                d_col[atomicAdd(&d_cursor[dd1.x], 1)] = s1.x;
            if ((unsigned)dd1.y < N_NODES && (unsigned)s1.y < N_NODES)
                d_col[atomicAdd(&d_cursor[dd1.y], 1)] = s1.y;
            if ((unsigned)dd1.z < N_NODES && (unsigned)s1.z < N_NODES)
                d_col[atomicAdd(&d_cursor[dd1.z], 1)] = s1.z;
            if ((unsigned)dd1.w < N_NODES && (unsigned)s1.w < N_NODES)
                d_col[atomicAdd(&d_cursor[dd1.w], 1)] = s1.w;
        }
    } else {
        int i = (blockIdx.x - EDGE_BLOCKS) * 256 + threadIdx.x;
        if (i < SCALE_VEC) {
            int node = i >> 2;
            float di = d_dinv[node];
            float4 v0 = ((const float4*)d_g1)[2 * i];
            float4 v1 = ((const float4*)d_g1)[2 * i + 1];
            __half2 h[4];
            h[0] = __floats2half2_rn(v0.x * di, v0.y * di);
            h[1] = __floats2half2_rn(v0.z * di, v0.w * di);
            h[2] = __floats2half2_rn(v1.x * di, v1.y * di);
            h[3] = __floats2half2_rn(v1.z * di, v1.w * di);
            ((uint4*)d_g1h)[i] = *(uint4*)h;
        }
    }
}

// ---------------- 5. layer-1 aggregate: 2 edges per warp-LDG (half2 lanes) ------------
// warp per node. grp = lane>>4 picks edge A/B; p = lane&15 picks half2 feature chunk.
__global__ void __launch_bounds__(256) k_agg1(const float* __restrict__ b1,
                                              const float* __restrict__ W2) {
    __shared__ float W2s[H1 * H2];
    int tid = threadIdx.x;
    for (int i = tid; i < H1 * H2; i += 256) W2s[i] = W2[i];
    __syncthreads();
    int wid = tid >> 5, lane = tid & 31;
    int node = blockIdx.x * 8 + wid;
    if (node >= N_NODES) return;

    int grp = lane >> 4, p = lane & 15;
    const __half2* G = (const __half2*)d_g1h;   // row = 16 half2
    float2 acc = make_float2(0.f, 0.f);
    if (grp == 0) {                              // self-loop once
        float2 sv = __half22float2(G[(size_t)node * 16 + p]);
        acc.x += sv.x; acc.y += sv.y;
    }
    int s = d_rowptr[node], e = d_rowptr[node + 1];
    int i = s + grp;
    for (; i + 6 < e; i += 8) {                  // 4 independent loads/lane
        float2 v0 = __half22float2(G[(size_t)d_col[i]     * 16 + p]);
        float2 v1 = __half22float2(G[(size_t)d_col[i + 2] * 16 + p]);
        float2 v2 = __half22float2(G[(size_t)d_col[i + 4] * 16 + p]);
        float2 v3 = __half22float2(G[(size_t)d_col[i + 6] * 16 + p]);
        acc.x += (v0.x + v1.x) + (v2.x + v3.x);
        acc.y += (v0.y + v1.y) + (v2.y + v3.y);
    }
    for (; i < e; i += 2) {
        float2 v = __half22float2(G[(size_t)d_col[i] * 16 + p]);
        acc.x += v.x; acc.y += v.y;
    }
    acc.x += __shfl_xor_sync(0xffffffffu, acc.x, 16);   // combine edge groups
    acc.y += __shfl_xor_sync(0xffffffffu, acc.y, 16);

    float di = d_dinv[node];
    float2 bb = ((const float2*)b1)[p];
    float2 h;                                    // h1[2p], h1[2p+1]
    h.x = fmaxf(di * acc.x + bb.x, 0.f);
    h.y = fmaxf(di * acc.y + bb.y, 0.f);

    // g2[node][f] = di * sum_c h1[c]*W2[c][f]; h1[2q]/[2q+1] live in lane q (dup at q+16)
    float o = 0.f;
    int f = p;                                   // f = lane&15
#pragma unroll
    for (int q = 0; q < 16; q++) {
        float hx = __shfl_sync(0xffffffffu, h.x, q);
        float hy = __shfl_sync(0xffffffffu, h.y, q);
        o = fmaf(hx, W2s[(2 * q) * H2 + f], o);
        o = fmaf(hy, W2s[(2 * q + 1) * H2 + f], o);
    }
    if (lane < H2) d_g2h[(size_t)node * H2 + f] = __float2half_rn(di * o);
}

// ---------------- 6. layer-2 aggregate: 4 edges per warp-LDG + mean-pool --------------
// warp per node. grp = lane>>3 (edge slot 0..3); p = lane&7 (half2 chunk of 32B row).
__global__ void __launch_bounds__(256) k_agg2(const float* __restrict__ b2,
                                              const int* __restrict__ batch) {
    int tid = threadIdx.x;
    int wid = tid >> 5, lane = tid & 31;
    int node = blockIdx.x * 8 + wid;
    if (node >= N_NODES) return;

    int grp = lane >> 3, p = lane & 7;
    const __half2* G = (const __half2*)d_g2h;    // row = 8 half2
    float2 acc = make_float2(0.f, 0.f);
    if (grp == 0) {
        float2 sv = __half22float2(G[(size_t)node * 8 + p]);
        acc.x += sv.x; acc.y += sv.y;
    }
    int s = d_rowptr[node], e = d_rowptr[node + 1];
    int i = s + grp;
    for (; i + 4 < e; i += 8) {                  // 2 independent loads/lane
        float2 v0 = __half22float2(G[(size_t)d_col[i]     * 8 + p]);
        float2 v1 = __half22float2(G[(size_t)d_col[i + 4] * 8 + p]);
        acc.x += v0.x + v1.x;
        acc.y += v0.y + v1.y;
    }
    for (; i < e; i += 4) {
        float2 v = __half22float2(G[(size_t)d_col[i] * 8 + p]);
        acc.x += v.x; acc.y += v.y;
    }
    acc.x += __shfl_xor_sync(0xffffffffu, acc.x, 8);
    acc.y += __shfl_xor_sync(0xffffffffu, acc.y, 8);
    acc.x += __shfl_xor_sync(0xffffffffu, acc.x, 16);
    acc.y += __shfl_xor_sync(0xffffffffu, acc.y, 16);

    float di = d_dinv[node];
    float2 bb = ((const float2*)b2)[p];
    float hx = fmaxf(di * acc.x + bb.x, 0.f);    // h2[2p]
    float hy = fmaxf(di * acc.y + bb.y, 0.f);    // h2[2p+1]

    int g = batch[node];
    if ((unsigned)g < N_GRAPHS && lane < 8) {
        atomicAdd(&d_pool[g * H2 + 2 * p], hx);
        atomicAdd(&d_pool[g * H2 + 2 * p + 1], hy);
    }
}

// ---------------- 7. output head ----------------
__global__ void k_out(const int* __restrict__ batch, const float* __restrict__ W3,
                      const float* __restrict__ b3, float* __restrict__ out) {
    int g = blockIdx.x * blockDim.x + threadIdx.x;
    if (g >= N_GRAPHS) return;
    int lo0 = 0, hi0 = N_NODES;
    while (lo0 < hi0) { int m = (lo0 + hi0) >> 1; if (batch[m] < g) lo0 = m + 1; else hi0 = m; }
    int lo1 = lo0, hi1 = N_NODES;
    while (lo1 < hi1) { int m = (lo1 + hi1) >> 1; if (batch[m] < g + 1) lo1 = m + 1; else hi1 = m; }
    float c = fmaxf((float)(lo1 - lo0), 1.f);
    float sm = 0.f;
#pragma unroll
    for (int j = 0; j < H2; j++) sm = fmaf(d_pool[g * H2 + j], W3[j], sm);
    out[g] = sm / c + b3[0];
}

// ---------------- launch ----------------
extern "C" void kernel_launch(void* const* d_in, const int* in_sizes, int n_in,
                              void* d_out, int out_size) {
    const float* x     = (const float*)d_in[0];
    const int*   ei    = (const int*)d_in[1];
    const int*   batch = (const int*)d_in[2];
    const float* W1    = (const float*)d_in[3];
    const float* b1    = (const float*)d_in[4];
    const float* W2    = (const float*)d_in[5];
    const float* b2    = (const float*)d_in[6];
    const float* W3    = (const float*)d_in[7];
    const float* b3    = (const float*)d_in[8];
    float* out = (float*)d_out;

    const int NB = (N_NODES + 7) / 8;

    k_zero<<<SCAN_BLOCKS, 256>>>();
    k_gemm_deg<<<GEMM_BLOCKS + EDGE_BLOCKS, 256>>>(x, W1, ei);
    k_scan<<<SCAN_BLOCKS, 256>>>();
    k_csr_scale<<<EDGE_BLOCKS + SCALE_BLOCKS, 256>>>(ei);
    k_agg1<<<NB, 256>>>(b1, W2);
    k_agg2<<<NB, 256>>>(b2, batch);
    k_out<<<(N_GRAPHS + 255) / 256, 256>>>(batch, W3, b3, out);
}